// round 14
// baseline (speedup 1.0000x reference)
#include <cuda_runtime.h>
#include <cuda_fp16.h>
#include <math.h>
#include <float.h>

#define NN 100000
#define EE 3200000
#define IND 64
#define HID 128
#define NCLS 10
#define NB ((NN + 127) / 128)

// prologue block ranges
#define PB1 ((EE + 255) / 256)
#define PB2 ((NN * IND / 4 + 255) / 256)
#define PB3 ((128 * (IND + HID) + 255) / 256)

// ---------------- scratch (device globals) ----------------------------------
__device__ __align__(16) __half d_xh [(size_t)NN * IND];
__device__ __align__(16) __half d_A1h[(size_t)NN * IND];
__device__ __align__(16) __half d_h1h[(size_t)NN * HID];
__device__ __align__(16) __half d_A2h[(size_t)NN * HID];
__device__ __align__(16) __half d_w1t[HID * IND];
__device__ __align__(16) __half d_w2t[HID * HID];
__device__ __align__(16) int2  d_epack[EE];
__device__ float d_rowsum[NN];
__device__ int   d_rowptr[NN + 1];
__device__ float d_part[(size_t)NB * 130];
__device__ float d_g[HID];
__device__ float d_Z;

// ---------------- mma helpers -------------------------------------------------
__device__ __forceinline__ void ldsm4(unsigned& r0, unsigned& r1,
                                      unsigned& r2, unsigned& r3, unsigned addr) {
    asm volatile("ldmatrix.sync.aligned.m8n8.x4.shared.b16 {%0,%1,%2,%3}, [%4];"
                 : "=r"(r0), "=r"(r1), "=r"(r2), "=r"(r3) : "r"(addr));
}
__device__ __forceinline__ void mma16816(float* c,
                                         unsigned a0, unsigned a1, unsigned a2, unsigned a3,
                                         unsigned b0, unsigned b1) {
    asm volatile("mma.sync.aligned.m16n8k16.row.col.f32.f16.f16.f32 "
                 "{%0,%1,%2,%3}, {%4,%5,%6,%7}, {%8,%9}, {%0,%1,%2,%3};"
                 : "+f"(c[0]), "+f"(c[1]), "+f"(c[2]), "+f"(c[3])
                 : "r"(a0), "r"(a1), "r"(a2), "r"(a3), "r"(b0), "r"(b1));
}

// ---------------- prologue -----------------------------------------------------
__global__ void k_prologue(const int* __restrict__ erows,
                           const int* __restrict__ ecols,
                           const float* __restrict__ evals,
                           const float* __restrict__ x,
                           const float* __restrict__ fc1_w,
                           const float* __restrict__ fc2_w) {
    int bid = blockIdx.x, tid = threadIdx.x;
    if (bid < PB1) {
        int i = bid * 256 + tid;
        if (i >= EE) return;
        int2 ep = make_int2(__ldg(ecols + i), __float_as_int(__ldg(evals + i)));
        __stcs(&d_epack[i], ep);
        int r1 = erows[i];
        int r0 = (i == 0) ? -1 : erows[i - 1];
        for (int r = r0 + 1; r <= r1; r++) d_rowptr[r] = i;
        if (i == EE - 1)
            for (int r = r1 + 1; r <= NN; r++) d_rowptr[r] = EE;
    } else if (bid < PB1 + PB2) {
        int i = (bid - PB1) * 256 + tid;
        if (i >= NN * IND / 4) return;
        float4 v = ((const float4*)x)[i];
        __half2 a = __floats2half2_rn(v.x, v.y);
        __half2 b = __floats2half2_rn(v.z, v.w);
        ((uint2*)d_xh)[i] = make_uint2(*(unsigned*)&a, *(unsigned*)&b);
    } else {
        int i = (bid - PB1 - PB2) * 256 + tid;
        if (i < 128 * IND) {
            int n = i / IND, k = i % IND;
            d_w1t[i] = __float2half(fc1_w[k * 128 + n]);
        } else if (i < 128 * (IND + HID)) {
            int j = i - 128 * IND;
            int n = j / HID, k = j % HID;
            d_w2t[j] = __float2half(fc2_w[k * 128 + n]);
        }
    }
}

// ---------------- gather FMA helper -------------------------------------------
__device__ __forceinline__ void fmaacc8(float* acc, const uint4& raw, float v) {
    const __half2* hp = (const __half2*)&raw;
#pragma unroll
    for (int j = 0; j < 4; j++) {
        float2 f = __half22float2(hp[j]);
        acc[2 * j]     += v * f.x;
        acc[2 * j + 1] += v * f.y;
    }
}

// ---------------- SpMM 64-wide: 8 lanes/edge, 16 edges/iter, 64-thr blocks ---
__global__ void k_spmm64() {
    int row = blockIdx.x * 2 + (threadIdx.x >> 5);
    if (row >= NN) return;
    const int lane = threadIdx.x & 31;
    const int grp = lane >> 3;
    const int boff = (lane & 7) * 8;
    const int s = d_rowptr[row], e = d_rowptr[row + 1];
    float acc[8];
#pragma unroll
    for (int j = 0; j < 8; j++) acc[j] = 0.f;
    float vs = 0.f;
    int i = s;
    for (; i + 16 <= e; i += 16) {
        int2 cv0 = __ldcs(&d_epack[i      + grp]);
        int2 cv1 = __ldcs(&d_epack[i + 4  + grp]);
        int2 cv2 = __ldcs(&d_epack[i + 8  + grp]);
        int2 cv3 = __ldcs(&d_epack[i + 12 + grp]);
        uint4 r0 = *(const uint4*)(d_xh + (size_t)cv0.x * IND + boff);
        uint4 r1 = *(const uint4*)(d_xh + (size_t)cv1.x * IND + boff);
        uint4 r2 = *(const uint4*)(d_xh + (size_t)cv2.x * IND + boff);
        uint4 r3 = *(const uint4*)(d_xh + (size_t)cv3.x * IND + boff);
        float v0 = __int_as_float(cv0.y), v1 = __int_as_float(cv1.y);
        float v2 = __int_as_float(cv2.y), v3 = __int_as_float(cv3.y);
        fmaacc8(acc, r0, v0);
        fmaacc8(acc, r1, v1);
        fmaacc8(acc, r2, v2);
        fmaacc8(acc, r3, v3);
        vs += (v0 + v1) + (v2 + v3);
    }
    for (; i < e; i += 4) {
        int idx = i + grp;
        int2 cv = (idx < e) ? __ldcs(&d_epack[idx]) : make_int2(0, 0);
        float v = __int_as_float(cv.y);
        uint4 raw = *(const uint4*)(d_xh + (size_t)cv.x * IND + boff);
        fmaacc8(acc, raw, v);
        vs += v;
    }
#pragma unroll
    for (int j = 0; j < 8; j++) {
        acc[j] += __shfl_xor_sync(0xFFFFFFFFu, acc[j], 8);
        acc[j] += __shfl_xor_sync(0xFFFFFFFFu, acc[j], 16);
    }
    if (lane < 8) {
        __half2 h0 = __floats2half2_rn(acc[0], acc[1]);
        __half2 h1 = __floats2half2_rn(acc[2], acc[3]);
        __half2 h2 = __floats2half2_rn(acc[4], acc[5]);
        __half2 h3 = __floats2half2_rn(acc[6], acc[7]);
        uint4 st = make_uint4(*(unsigned*)&h0, *(unsigned*)&h1,
                              *(unsigned*)&h2, *(unsigned*)&h3);
        __stcs((uint4*)(d_A1h + (size_t)row * IND + lane * 8), st);
    }
    vs += __shfl_xor_sync(0xFFFFFFFFu, vs, 8);
    vs += __shfl_xor_sync(0xFFFFFFFFu, vs, 16);
    if (lane == 0) d_rowsum[row] = vs;
}

// ---------------- SpMM 128-wide: 16 lanes/edge, 8 edges/iter, 64-thr blocks --
__global__ void k_spmm128() {
    int row = blockIdx.x * 2 + (threadIdx.x >> 5);
    if (row >= NN) return;
    const int lane = threadIdx.x & 31;
    const int half = lane >> 4;
    const int boff = (lane & 15) * 8;
    const int s = d_rowptr[row], e = d_rowptr[row + 1];
    float acc[8];
#pragma unroll
    for (int j = 0; j < 8; j++) acc[j] = 0.f;
    int i = s;
    for (; i + 8 <= e; i += 8) {
        int2 cv0 = __ldcs(&d_epack[i     + half]);
        int2 cv1 = __ldcs(&d_epack[i + 2 + half]);
        int2 cv2 = __ldcs(&d_epack[i + 4 + half]);
        int2 cv3 = __ldcs(&d_epack[i + 6 + half]);
        uint4 r0 = *(const uint4*)(d_h1h + (size_t)cv0.x * HID + boff);
        uint4 r1 = *(const uint4*)(d_h1h + (size_t)cv1.x * HID + boff);
        uint4 r2 = *(const uint4*)(d_h1h + (size_t)cv2.x * HID + boff);
        uint4 r3 = *(const uint4*)(d_h1h + (size_t)cv3.x * HID + boff);
        fmaacc8(acc, r0, __int_as_float(cv0.y));
        fmaacc8(acc, r1, __int_as_float(cv1.y));
        fmaacc8(acc, r2, __int_as_float(cv2.y));
        fmaacc8(acc, r3, __int_as_float(cv3.y));
    }
    for (; i < e; i += 2) {
        int idx = i + half;
        int2 cv = (idx < e) ? __ldcs(&d_epack[idx]) : make_int2(0, 0);
        uint4 raw = *(const uint4*)(d_h1h + (size_t)cv.x * HID + boff);
        fmaacc8(acc, raw, __int_as_float(cv.y));
    }
#pragma unroll
    for (int j = 0; j < 8; j++)
        acc[j] += __shfl_xor_sync(0xFFFFFFFFu, acc[j], 16);
    if (lane < 16) {
        __half2 h0 = __floats2half2_rn(acc[0], acc[1]);
        __half2 h1 = __floats2half2_rn(acc[2], acc[3]);
        __half2 h2 = __floats2half2_rn(acc[4], acc[5]);
        __half2 h3 = __floats2half2_rn(acc[6], acc[7]);
        uint4 st = make_uint4(*(unsigned*)&h0, *(unsigned*)&h1,
                              *(unsigned*)&h2, *(unsigned*)&h3);
        __stcs((uint4*)(d_A2h + (size_t)row * HID + lane * 8), st);
    }
}

// ---------------- tensor-core GEMM --------------------------------------------
template <int K, bool SECOND>
__global__ void __launch_bounds__(256, 2)
k_gemm_mma(const __half* __restrict__ Ag, const __half* __restrict__ Wt,
           const float* __restrict__ bias,
           const float* __restrict__ att_w, const float* __restrict__ att_b) {
    extern __shared__ __align__(16) char smraw[];
    __half* A_sh = (__half*)smraw;
    __half* W_sh = A_sh + 128 * K;
    float* bias_sh = (float*)(W_sh + 128 * K);
    float* aw_sh = bias_sh + 128;
    float* s_sh  = aw_sh + 128;
    float* g_sh  = s_sh + 128;
    float* wmax  = g_sh + 128;
    float* m_sh  = wmax + 8;
    float* z_sh  = m_sh + 1;

    const int tid = threadIdx.x;
    const int r0 = blockIdx.x * 128;
    const int w = tid >> 5, lane = tid & 31;
    const int q = lane & 3, g8 = lane >> 2;

    if (tid < 128) {
        bias_sh[tid] = bias[tid];
        if (SECOND) { aw_sh[tid] = att_w[tid]; g_sh[tid] = 0.f; }
    }
    if (SECOND && tid == 128) z_sh[0] = 0.f;

    constexpr int GPR = K / 8;
    {
        const uint4* src = (const uint4*)Ag;
#pragma unroll
        for (int i = 0; i < 128 * GPR / 256; i++) {
            int idx = i * 256 + tid;
            int row = idx / GPR, g = idx % GPR;
            int gr = r0 + row;
            uint4 v = make_uint4(0, 0, 0, 0);
            if (gr < NN) v = __ldcs(&src[(size_t)gr * GPR + g]);
            *(uint4*)&A_sh[row * K + ((g ^ (row & 7)) << 3)] = v;
        }
        const uint4* ws = (const uint4*)Wt;
#pragma unroll
        for (int i = 0; i < 128 * GPR / 256; i++) {
            int idx = i * 256 + tid;
            int row = idx / GPR, g = idx % GPR;
            *(uint4*)&W_sh[row * K + ((g ^ (row & 7)) << 3)] = ws[idx];
        }
    }
    __syncthreads();

    unsigned aBase = (unsigned)__cvta_generic_to_shared(A_sh);
    unsigned wBase = (unsigned)__cvta_generic_to_shared(W_sh);

    const int rowA   = w * 16 + ((lane >> 3) & 1) * 8 + (lane & 7);
    const int khalfA = lane >> 4;
    const int rowBoff = ((lane >> 4) & 1) * 8 + (lane & 7);
    const int khalfB  = (lane >> 3) & 1;
    const int l7 = lane & 7;

    float acc[16][4];
#pragma unroll
    for (int t = 0; t < 16; t++)
#pragma unroll
        for (int p = 0; p < 4; p++) acc[t][p] = 0.f;

#pragma unroll
    for (int kc = 0; kc < K; kc += 16) {
        unsigned a0, a1, a2, a3;
        int grpA = (kc >> 3) + khalfA;
        ldsm4(a0, a1, a2, a3,
              aBase + (unsigned)(rowA * K + ((grpA ^ (rowA & 7)) << 3)) * 2u);
        int grpB = (kc >> 3) + khalfB;
#pragma unroll
        for (int jj = 0; jj < 8; jj++) {
            int rowB = jj * 16 + rowBoff;
            unsigned b0, b1, b2, b3;
            ldsm4(b0, b1, b2, b3,
                  wBase + (unsigned)(rowB * K + ((grpB ^ l7) << 3)) * 2u);
            mma16816(acc[2 * jj],     a0, a1, a2, a3, b0, b1);
            mma16816(acc[2 * jj + 1], a0, a1, a2, a3, b2, b3);
        }
    }

    const int lr0 = w * 16 + g8, lr1 = lr0 + 8;
    const int gr0 = r0 + lr0, gr1 = r0 + lr1;
    const float rs0 = (gr0 < NN) ? d_rowsum[gr0] : 0.f;
    const float rs1 = (gr1 < NN) ? d_rowsum[gr1] : 0.f;

#pragma unroll
    for (int t = 0; t < 16; t++) {
#pragma unroll
        for (int p = 0; p < 2; p++) {
            float b = bias_sh[8 * t + 2 * q + p];
            acc[t][p]     = fmaxf(acc[t][p]     + rs0 * b, 0.f);
            acc[t][2 + p] = fmaxf(acc[t][2 + p] + rs1 * b, 0.f);
        }
    }

    if (!SECOND) {
#pragma unroll
        for (int t = 0; t < 16; t++) {
            int col = 8 * t + 2 * q;
            if (gr0 < NN) {
                __half2 h = __floats2half2_rn(acc[t][0], acc[t][1]);
                *(__half2*)&d_h1h[(size_t)gr0 * HID + col] = h;
            }
            if (gr1 < NN) {
                __half2 h = __floats2half2_rn(acc[t][2], acc[t][3]);
                *(__half2*)&d_h1h[(size_t)gr1 * HID + col] = h;
            }
        }
        return;
    } else {
        float sc0 = 0.f, sc1 = 0.f;
#pragma unroll
        for (int t = 0; t < 16; t++) {
            int col = 8 * t + 2 * q;
            if (gr0 < NN) {
                float2 f = __half22float2(*(const __half2*)&d_h1h[(size_t)gr0 * HID + col]);
                acc[t][0] += f.x; acc[t][1] += f.y;
            }
            if (gr1 < NN) {
                float2 f = __half22float2(*(const __half2*)&d_h1h[(size_t)gr1 * HID + col]);
                acc[t][2] += f.x; acc[t][3] += f.y;
            }
            float aw0 = aw_sh[col], aw1 = aw_sh[col + 1];
            sc0 += acc[t][0] * aw0 + acc[t][1] * aw1;
            sc1 += acc[t][2] * aw0 + acc[t][3] * aw1;
        }
        sc0 += __shfl_xor_sync(0xFFFFFFFFu, sc0, 1);
        sc0 += __shfl_xor_sync(0xFFFFFFFFu, sc0, 2);
        sc1 += __shfl_xor_sync(0xFFFFFFFFu, sc1, 1);
        sc1 += __shfl_xor_sync(0xFFFFFFFFu, sc1, 2);
        float ab = att_b[0];
        if (q == 0) {
            s_sh[lr0] = (gr0 < NN) ? (sc0 + ab) : -FLT_MAX;
            s_sh[lr1] = (gr1 < NN) ? (sc1 + ab) : -FLT_MAX;
        }
        __syncthreads();
        {
            float v = s_sh[tid & 127];
#pragma unroll
            for (int off = 16; off; off >>= 1)
                v = fmaxf(v, __shfl_xor_sync(0xFFFFFFFFu, v, off));
            if (lane == 0) wmax[w] = v;
        }
        __syncthreads();
        if (tid == 0) {
            float m = wmax[0];
#pragma unroll
            for (int i = 1; i < 8; i++) m = fmaxf(m, wmax[i]);
            m_sh[0] = m;
        }
        __syncthreads();
        const float mb = m_sh[0];
        const float e0 = __expf(s_sh[lr0] - mb);
        const float e1 = __expf(s_sh[lr1] - mb);
#pragma unroll
        for (int t = 0; t < 16; t++) {
            acc[t][0] = e0 * acc[t][0] + e1 * acc[t][2];
            acc[t][1] = e0 * acc[t][1] + e1 * acc[t][3];
        }
#pragma unroll
        for (int off = 4; off <= 16; off <<= 1) {
#pragma unroll
            for (int t = 0; t < 16; t++) {
                acc[t][0] += __shfl_xor_sync(0xFFFFFFFFu, acc[t][0], off);
                acc[t][1] += __shfl_xor_sync(0xFFFFFFFFu, acc[t][1], off);
            }
        }
        if (lane < 4) {
#pragma unroll
            for (int t = 0; t < 16; t++) {
                atomicAdd(&g_sh[8 * t + 2 * lane],     acc[t][0]);
                atomicAdd(&g_sh[8 * t + 2 * lane + 1], acc[t][1]);
            }
        }
        float ze = (q == 0) ? (e0 + e1) : 0.f;
        ze += __shfl_xor_sync(0xFFFFFFFFu, ze, 4);
        ze += __shfl_xor_sync(0xFFFFFFFFu, ze, 8);
        ze += __shfl_xor_sync(0xFFFFFFFFu, ze, 16);
        if (lane == 0) atomicAdd(z_sh, ze);
        __syncthreads();
        float* pp = d_part + (size_t)blockIdx.x * 130;
        if (tid < 128) pp[tid] = g_sh[tid];
        if (tid == 128) pp[128] = z_sh[0];
        if (tid == 129) pp[129] = m_sh[0];
    }
}

// ---------------- combine: block j<128 -> g[j]; j==128 -> Z (parallel) -------
__global__ void k_combine() {
    __shared__ float red[256];
    __shared__ float Msh;
    int tid = threadIdx.x, j = blockIdx.x;
    float lm = -FLT_MAX;
    for (int b = tid; b < NB; b += 256)
        lm = fmaxf(lm, d_part[(size_t)b * 130 + 129]);
    red[tid] = lm;
    __syncthreads();
    for (int s = 128; s; s >>= 1) {
        if (tid < s) red[tid] = fmaxf(red[tid], red[tid + s]);
        __syncthreads();
    }
    if (tid == 0) Msh = red[0];
    __syncthreads();
    float M = Msh;
    int col = (j < 128) ? j : 128;
    float acc = 0.f;
    for (int b = tid; b < NB; b += 256) {
        float mb = d_part[(size_t)b * 130 + 129];
        acc += __expf(mb - M) * d_part[(size_t)b * 130 + col];
    }
    red[tid] = acc;
    __syncthreads();
    for (int s = 128; s; s >>= 1) {
        if (tid < s) red[tid] += red[tid + s];
        __syncthreads();
    }
    if (tid == 0) {
        if (j < 128) d_g[j] = red[0];
        else d_Z = red[0];
    }
}

// ---------------- final --------------------------------------------------------
__global__ void k_final(const float* __restrict__ cls_w,
                        const float* __restrict__ cls_b,
                        float* __restrict__ out) {
    int c = threadIdx.x;
    if (c < NCLS) {
        float invZ = 1.f / d_Z;
        float acc = cls_b[c];
        for (int k = 0; k < HID; k++)
            acc += (d_g[k] * invZ) * cls_w[k * NCLS + c];
        out[c] = acc;
    }
}

// ---------------- launch ---------------------------------------------------------
extern "C" void kernel_launch(void* const* d_in, const int* in_sizes, int n_in,
                              void* d_out, int out_size) {
    const float* x     = (const float*)d_in[0];
    const int*   erows = (const int*)  d_in[1];
    const int*   ecols = (const int*)  d_in[2];
    const float* evals = (const float*)d_in[3];
    const float* fc1_w = (const float*)d_in[4];
    const float* fc1_b = (const float*)d_in[5];
    const float* fc2_w = (const float*)d_in[6];
    const float* fc2_b = (const float*)d_in[7];
    const float* att_w = (const float*)d_in[8];
    const float* att_b = (const float*)d_in[9];
    const float* cls_w = (const float*)d_in[10];
    const float* cls_b = (const float*)d_in[11];
    float* out = (float*)d_out;

    __half* pA1 = nullptr; __half* pA2 = nullptr;
    __half* pW1 = nullptr; __half* pW2 = nullptr;
    cudaGetSymbolAddress((void**)&pA1, d_A1h);
    cudaGetSymbolAddress((void**)&pA2, d_A2h);
    cudaGetSymbolAddress((void**)&pW1, d_w1t);
    cudaGetSymbolAddress((void**)&pW2, d_w2t);

    const int extras = (128 * 4 + 8 + 2) * 4;
    const int smem1 = 128 * IND * 2 * 2 + extras;
    const int smem2 = 128 * HID * 2 * 2 + extras;
    cudaFuncSetAttribute(k_gemm_mma<IND, false>,
                         cudaFuncAttributeMaxDynamicSharedMemorySize, smem1);
    cudaFuncSetAttribute(k_gemm_mma<HID, true>,
                         cudaFuncAttributeMaxDynamicSharedMemorySize, smem2);

    k_prologue<<<PB1 + PB2 + PB3, 256>>>(erows, ecols, evals, x, fc1_w, fc2_w);
    k_spmm64<<<(NN + 1) / 2, 64>>>();
    k_gemm_mma<IND, false><<<NB, 256, smem1>>>(pA1, pW1, fc1_b, nullptr, nullptr);
    k_spmm128<<<(NN + 1) / 2, 64>>>();
    k_gemm_mma<HID, true><<<NB, 256, smem2>>>(pA2, pW2, fc2_b, att_w, att_b);
    k_combine<<<129, 256>>>();
    k_final<<<1, 32>>>(cls_w, cls_b, out);
}

// round 15
// speedup vs baseline: 1.0209x; 1.0209x over previous
#include <cuda_runtime.h>
#include <cuda_fp16.h>
#include <math.h>
#include <float.h>

#define NN 100000
#define EE 3200000
#define IND 64
#define HID 128
#define NCLS 10
#define NB ((NN + 127) / 128)

// prologue block ranges
#define PB1 ((EE + 255) / 256)
#define PB2 ((NN * IND / 4 + 255) / 256)
#define PB3 ((128 * (IND + HID) + 255) / 256)

// ---------------- scratch (device globals) ----------------------------------
__device__ __align__(16) __half d_xh [(size_t)NN * IND];
__device__ __align__(16) __half d_A1h[(size_t)NN * IND];
__device__ __align__(16) __half d_h1h[(size_t)NN * HID];
__device__ __align__(16) __half d_A2h[(size_t)NN * HID];
__device__ __align__(16) __half d_w1t[HID * IND];
__device__ __align__(16) __half d_w2t[HID * HID];
__device__ __align__(16) int2  d_epack[EE];
__device__ float d_rowsum[NN];
__device__ int   d_rowptr[NN + 1];
__device__ float d_part[(size_t)NB * 130];
__device__ float d_g[HID];
__device__ float d_Z;

// ---------------- mma helpers -------------------------------------------------
__device__ __forceinline__ void ldsm4(unsigned& r0, unsigned& r1,
                                      unsigned& r2, unsigned& r3, unsigned addr) {
    asm volatile("ldmatrix.sync.aligned.m8n8.x4.shared.b16 {%0,%1,%2,%3}, [%4];"
                 : "=r"(r0), "=r"(r1), "=r"(r2), "=r"(r3) : "r"(addr));
}
__device__ __forceinline__ void mma16816(float* c,
                                         unsigned a0, unsigned a1, unsigned a2, unsigned a3,
                                         unsigned b0, unsigned b1) {
    asm volatile("mma.sync.aligned.m16n8k16.row.col.f32.f16.f16.f32 "
                 "{%0,%1,%2,%3}, {%4,%5,%6,%7}, {%8,%9}, {%0,%1,%2,%3};"
                 : "+f"(c[0]), "+f"(c[1]), "+f"(c[2]), "+f"(c[3])
                 : "r"(a0), "r"(a1), "r"(a2), "r"(a3), "r"(b0), "r"(b1));
}

// ---------------- prologue -----------------------------------------------------
__global__ void k_prologue(const int* __restrict__ erows,
                           const int* __restrict__ ecols,
                           const float* __restrict__ evals,
                           const float* __restrict__ x,
                           const float* __restrict__ fc1_w,
                           const float* __restrict__ fc2_w) {
    int bid = blockIdx.x, tid = threadIdx.x;
    if (bid < PB1) {
        int i = bid * 256 + tid;
        if (i >= EE) return;
        d_epack[i] = make_int2(__ldg(ecols + i), __float_as_int(__ldg(evals + i)));
        int r1 = erows[i];
        int r0 = (i == 0) ? -1 : erows[i - 1];
        for (int r = r0 + 1; r <= r1; r++) d_rowptr[r] = i;
        if (i == EE - 1)
            for (int r = r1 + 1; r <= NN; r++) d_rowptr[r] = EE;
    } else if (bid < PB1 + PB2) {
        int i = (bid - PB1) * 256 + tid;
        if (i >= NN * IND / 4) return;
        float4 v = ((const float4*)x)[i];
        __half2 a = __floats2half2_rn(v.x, v.y);
        __half2 b = __floats2half2_rn(v.z, v.w);
        ((uint2*)d_xh)[i] = make_uint2(*(unsigned*)&a, *(unsigned*)&b);
    } else {
        int i = (bid - PB1 - PB2) * 256 + tid;
        if (i < 128 * IND) {
            int n = i / IND, k = i % IND;
            d_w1t[i] = __float2half(fc1_w[k * 128 + n]);
        } else if (i < 128 * (IND + HID)) {
            int j = i - 128 * IND;
            int n = j / HID, k = j % HID;
            d_w2t[j] = __float2half(fc2_w[k * 128 + n]);
        }
    }
}

// ---------------- gather FMA helper -------------------------------------------
__device__ __forceinline__ void fmaacc8(float* acc, const uint4& raw, float v) {
    const __half2* hp = (const __half2*)&raw;
#pragma unroll
    for (int j = 0; j < 4; j++) {
        float2 f = __half22float2(hp[j]);
        acc[2 * j]     += v * f.x;
        acc[2 * j + 1] += v * f.y;
    }
}

// ---------------- SpMM 64-wide: 8 lanes/edge, 16 edges/iter, 64-thr blocks ---
__global__ void k_spmm64() {
    int row = blockIdx.x * 2 + (threadIdx.x >> 5);
    if (row >= NN) return;
    const int lane = threadIdx.x & 31;
    const int grp = lane >> 3;
    const int boff = (lane & 7) * 8;
    const int s = d_rowptr[row], e = d_rowptr[row + 1];
    float acc[8];
#pragma unroll
    for (int j = 0; j < 8; j++) acc[j] = 0.f;
    float vs = 0.f;
    int i = s;
    for (; i + 16 <= e; i += 16) {
        int2 cv0 = __ldg(&d_epack[i      + grp]);
        int2 cv1 = __ldg(&d_epack[i + 4  + grp]);
        int2 cv2 = __ldg(&d_epack[i + 8  + grp]);
        int2 cv3 = __ldg(&d_epack[i + 12 + grp]);
        uint4 r0 = *(const uint4*)(d_xh + (size_t)cv0.x * IND + boff);
        uint4 r1 = *(const uint4*)(d_xh + (size_t)cv1.x * IND + boff);
        uint4 r2 = *(const uint4*)(d_xh + (size_t)cv2.x * IND + boff);
        uint4 r3 = *(const uint4*)(d_xh + (size_t)cv3.x * IND + boff);
        float v0 = __int_as_float(cv0.y), v1 = __int_as_float(cv1.y);
        float v2 = __int_as_float(cv2.y), v3 = __int_as_float(cv3.y);
        fmaacc8(acc, r0, v0);
        fmaacc8(acc, r1, v1);
        fmaacc8(acc, r2, v2);
        fmaacc8(acc, r3, v3);
        vs += (v0 + v1) + (v2 + v3);
    }
    for (; i < e; i += 4) {
        int idx = i + grp;
        int2 cv = (idx < e) ? __ldg(&d_epack[idx]) : make_int2(0, 0);
        float v = __int_as_float(cv.y);
        uint4 raw = *(const uint4*)(d_xh + (size_t)cv.x * IND + boff);
        fmaacc8(acc, raw, v);
        vs += v;
    }
#pragma unroll
    for (int j = 0; j < 8; j++) {
        acc[j] += __shfl_xor_sync(0xFFFFFFFFu, acc[j], 8);
        acc[j] += __shfl_xor_sync(0xFFFFFFFFu, acc[j], 16);
    }
    if (lane < 8) {
        __half2 h0 = __floats2half2_rn(acc[0], acc[1]);
        __half2 h1 = __floats2half2_rn(acc[2], acc[3]);
        __half2 h2 = __floats2half2_rn(acc[4], acc[5]);
        __half2 h3 = __floats2half2_rn(acc[6], acc[7]);
        *(uint4*)(d_A1h + (size_t)row * IND + lane * 8) =
            make_uint4(*(unsigned*)&h0, *(unsigned*)&h1,
                       *(unsigned*)&h2, *(unsigned*)&h3);
    }
    vs += __shfl_xor_sync(0xFFFFFFFFu, vs, 8);
    vs += __shfl_xor_sync(0xFFFFFFFFu, vs, 16);
    if (lane == 0) d_rowsum[row] = vs;
}

// ---------------- SpMM 128-wide: 16 lanes/edge, 8 edges/iter, 64-thr blocks --
__global__ void k_spmm128() {
    int row = blockIdx.x * 2 + (threadIdx.x >> 5);
    if (row >= NN) return;
    const int lane = threadIdx.x & 31;
    const int half = lane >> 4;
    const int boff = (lane & 15) * 8;
    const int s = d_rowptr[row], e = d_rowptr[row + 1];
    float acc[8];
#pragma unroll
    for (int j = 0; j < 8; j++) acc[j] = 0.f;
    int i = s;
    for (; i + 8 <= e; i += 8) {
        int2 cv0 = __ldg(&d_epack[i     + half]);
        int2 cv1 = __ldg(&d_epack[i + 2 + half]);
        int2 cv2 = __ldg(&d_epack[i + 4 + half]);
        int2 cv3 = __ldg(&d_epack[i + 6 + half]);
        uint4 r0 = *(const uint4*)(d_h1h + (size_t)cv0.x * HID + boff);
        uint4 r1 = *(const uint4*)(d_h1h + (size_t)cv1.x * HID + boff);
        uint4 r2 = *(const uint4*)(d_h1h + (size_t)cv2.x * HID + boff);
        uint4 r3 = *(const uint4*)(d_h1h + (size_t)cv3.x * HID + boff);
        fmaacc8(acc, r0, __int_as_float(cv0.y));
        fmaacc8(acc, r1, __int_as_float(cv1.y));
        fmaacc8(acc, r2, __int_as_float(cv2.y));
        fmaacc8(acc, r3, __int_as_float(cv3.y));
    }
    for (; i < e; i += 2) {
        int idx = i + half;
        int2 cv = (idx < e) ? __ldg(&d_epack[idx]) : make_int2(0, 0);
        uint4 raw = *(const uint4*)(d_h1h + (size_t)cv.x * HID + boff);
        fmaacc8(acc, raw, __int_as_float(cv.y));
    }
#pragma unroll
    for (int j = 0; j < 8; j++)
        acc[j] += __shfl_xor_sync(0xFFFFFFFFu, acc[j], 16);
    if (lane < 16) {
        __half2 h0 = __floats2half2_rn(acc[0], acc[1]);
        __half2 h1 = __floats2half2_rn(acc[2], acc[3]);
        __half2 h2 = __floats2half2_rn(acc[4], acc[5]);
        __half2 h3 = __floats2half2_rn(acc[6], acc[7]);
        *(uint4*)(d_A2h + (size_t)row * HID + lane * 8) =
            make_uint4(*(unsigned*)&h0, *(unsigned*)&h1,
                       *(unsigned*)&h2, *(unsigned*)&h3);
    }
}

// ---------------- tensor-core GEMM --------------------------------------------
template <int K, bool SECOND>
__global__ void __launch_bounds__(256, 2)
k_gemm_mma(const __half* __restrict__ Ag, const __half* __restrict__ Wt,
           const float* __restrict__ bias,
           const float* __restrict__ att_w, const float* __restrict__ att_b) {
    extern __shared__ __align__(16) char smraw[];
    __half* A_sh = (__half*)smraw;
    __half* W_sh = A_sh + 128 * K;
    float* bias_sh = (float*)(W_sh + 128 * K);
    float* aw_sh = bias_sh + 128;
    float* s_sh  = aw_sh + 128;
    float* g_sh  = s_sh + 128;
    float* wmax  = g_sh + 128;
    float* m_sh  = wmax + 8;
    float* z_sh  = m_sh + 1;

    const int tid = threadIdx.x;
    const int r0 = blockIdx.x * 128;
    const int w = tid >> 5, lane = tid & 31;
    const int q = lane & 3, g8 = lane >> 2;

    if (tid < 128) {
        bias_sh[tid] = bias[tid];
        if (SECOND) { aw_sh[tid] = att_w[tid]; g_sh[tid] = 0.f; }
    }
    if (SECOND && tid == 128) z_sh[0] = 0.f;

    constexpr int GPR = K / 8;
    {
        const uint4* src = (const uint4*)Ag;
#pragma unroll
        for (int i = 0; i < 128 * GPR / 256; i++) {
            int idx = i * 256 + tid;
            int row = idx / GPR, g = idx % GPR;
            int gr = r0 + row;
            uint4 v = make_uint4(0, 0, 0, 0);
            if (gr < NN) v = src[(size_t)gr * GPR + g];
            *(uint4*)&A_sh[row * K + ((g ^ (row & 7)) << 3)] = v;
        }
        const uint4* ws = (const uint4*)Wt;
#pragma unroll
        for (int i = 0; i < 128 * GPR / 256; i++) {
            int idx = i * 256 + tid;
            int row = idx / GPR, g = idx % GPR;
            *(uint4*)&W_sh[row * K + ((g ^ (row & 7)) << 3)] = ws[idx];
        }
    }
    __syncthreads();

    unsigned aBase = (unsigned)__cvta_generic_to_shared(A_sh);
    unsigned wBase = (unsigned)__cvta_generic_to_shared(W_sh);

    const int rowA   = w * 16 + ((lane >> 3) & 1) * 8 + (lane & 7);
    const int khalfA = lane >> 4;
    const int rowBoff = ((lane >> 4) & 1) * 8 + (lane & 7);
    const int khalfB  = (lane >> 3) & 1;
    const int l7 = lane & 7;

    float acc[16][4];
#pragma unroll
    for (int t = 0; t < 16; t++)
#pragma unroll
        for (int p = 0; p < 4; p++) acc[t][p] = 0.f;

#pragma unroll
    for (int kc = 0; kc < K; kc += 16) {
        unsigned a0, a1, a2, a3;
        int grpA = (kc >> 3) + khalfA;
        ldsm4(a0, a1, a2, a3,
              aBase + (unsigned)(rowA * K + ((grpA ^ (rowA & 7)) << 3)) * 2u);
        int grpB = (kc >> 3) + khalfB;
#pragma unroll
        for (int jj = 0; jj < 8; jj++) {
            int rowB = jj * 16 + rowBoff;
            unsigned b0, b1, b2, b3;
            ldsm4(b0, b1, b2, b3,
                  wBase + (unsigned)(rowB * K + ((grpB ^ l7) << 3)) * 2u);
            mma16816(acc[2 * jj],     a0, a1, a2, a3, b0, b1);
            mma16816(acc[2 * jj + 1], a0, a1, a2, a3, b2, b3);
        }
    }

    const int lr0 = w * 16 + g8, lr1 = lr0 + 8;
    const int gr0 = r0 + lr0, gr1 = r0 + lr1;
    const float rs0 = (gr0 < NN) ? d_rowsum[gr0] : 0.f;
    const float rs1 = (gr1 < NN) ? d_rowsum[gr1] : 0.f;

#pragma unroll
    for (int t = 0; t < 16; t++) {
#pragma unroll
        for (int p = 0; p < 2; p++) {
            float b = bias_sh[8 * t + 2 * q + p];
            acc[t][p]     = fmaxf(acc[t][p]     + rs0 * b, 0.f);
            acc[t][2 + p] = fmaxf(acc[t][2 + p] + rs1 * b, 0.f);
        }
    }

    if (!SECOND) {
#pragma unroll
        for (int t = 0; t < 16; t++) {
            int col = 8 * t + 2 * q;
            if (gr0 < NN) {
                __half2 h = __floats2half2_rn(acc[t][0], acc[t][1]);
                *(__half2*)&d_h1h[(size_t)gr0 * HID + col] = h;
            }
            if (gr1 < NN) {
                __half2 h = __floats2half2_rn(acc[t][2], acc[t][3]);
                *(__half2*)&d_h1h[(size_t)gr1 * HID + col] = h;
            }
        }
        return;
    } else {
        float sc0 = 0.f, sc1 = 0.f;
#pragma unroll
        for (int t = 0; t < 16; t++) {
            int col = 8 * t + 2 * q;
            if (gr0 < NN) {
                float2 f = __half22float2(*(const __half2*)&d_h1h[(size_t)gr0 * HID + col]);
                acc[t][0] += f.x; acc[t][1] += f.y;
            }
            if (gr1 < NN) {
                float2 f = __half22float2(*(const __half2*)&d_h1h[(size_t)gr1 * HID + col]);
                acc[t][2] += f.x; acc[t][3] += f.y;
            }
            float aw0 = aw_sh[col], aw1 = aw_sh[col + 1];
            sc0 += acc[t][0] * aw0 + acc[t][1] * aw1;
            sc1 += acc[t][2] * aw0 + acc[t][3] * aw1;
        }
        sc0 += __shfl_xor_sync(0xFFFFFFFFu, sc0, 1);
        sc0 += __shfl_xor_sync(0xFFFFFFFFu, sc0, 2);
        sc1 += __shfl_xor_sync(0xFFFFFFFFu, sc1, 1);
        sc1 += __shfl_xor_sync(0xFFFFFFFFu, sc1, 2);
        float ab = att_b[0];
        if (q == 0) {
            s_sh[lr0] = (gr0 < NN) ? (sc0 + ab) : -FLT_MAX;
            s_sh[lr1] = (gr1 < NN) ? (sc1 + ab) : -FLT_MAX;
        }
        __syncthreads();
        {
            float v = s_sh[tid & 127];
#pragma unroll
            for (int off = 16; off; off >>= 1)
                v = fmaxf(v, __shfl_xor_sync(0xFFFFFFFFu, v, off));
            if (lane == 0) wmax[w] = v;
        }
        __syncthreads();
        if (tid == 0) {
            float m = wmax[0];
#pragma unroll
            for (int i = 1; i < 8; i++) m = fmaxf(m, wmax[i]);
            m_sh[0] = m;
        }
        __syncthreads();
        const float mb = m_sh[0];
        const float e0 = __expf(s_sh[lr0] - mb);
        const float e1 = __expf(s_sh[lr1] - mb);
#pragma unroll
        for (int t = 0; t < 16; t++) {
            acc[t][0] = e0 * acc[t][0] + e1 * acc[t][2];
            acc[t][1] = e0 * acc[t][1] + e1 * acc[t][3];
        }
#pragma unroll
        for (int off = 4; off <= 16; off <<= 1) {
#pragma unroll
            for (int t = 0; t < 16; t++) {
                acc[t][0] += __shfl_xor_sync(0xFFFFFFFFu, acc[t][0], off);
                acc[t][1] += __shfl_xor_sync(0xFFFFFFFFu, acc[t][1], off);
            }
        }
        if (lane < 4) {
#pragma unroll
            for (int t = 0; t < 16; t++) {
                atomicAdd(&g_sh[8 * t + 2 * lane],     acc[t][0]);
                atomicAdd(&g_sh[8 * t + 2 * lane + 1], acc[t][1]);
            }
        }
        float ze = (q == 0) ? (e0 + e1) : 0.f;
        ze += __shfl_xor_sync(0xFFFFFFFFu, ze, 4);
        ze += __shfl_xor_sync(0xFFFFFFFFu, ze, 8);
        ze += __shfl_xor_sync(0xFFFFFFFFu, ze, 16);
        if (lane == 0) atomicAdd(z_sh, ze);
        __syncthreads();
        float* pp = d_part + (size_t)blockIdx.x * 130;
        if (tid < 128) pp[tid] = g_sh[tid];
        if (tid == 128) pp[128] = z_sh[0];
        if (tid == 129) pp[129] = m_sh[0];
    }
}

// ---------------- combine: block j<128 -> g[j]; j==128 -> Z (parallel) -------
__global__ void k_combine() {
    __shared__ float red[256];
    __shared__ float Msh;
    int tid = threadIdx.x, j = blockIdx.x;
    float lm = -FLT_MAX;
    for (int b = tid; b < NB; b += 256)
        lm = fmaxf(lm, d_part[(size_t)b * 130 + 129]);
    red[tid] = lm;
    __syncthreads();
    for (int s = 128; s; s >>= 1) {
        if (tid < s) red[tid] = fmaxf(red[tid], red[tid + s]);
        __syncthreads();
    }
    if (tid == 0) Msh = red[0];
    __syncthreads();
    float M = Msh;
    int col = (j < 128) ? j : 128;
    float acc = 0.f;
    for (int b = tid; b < NB; b += 256) {
        float mb = d_part[(size_t)b * 130 + 129];
        acc += __expf(mb - M) * d_part[(size_t)b * 130 + col];
    }
    red[tid] = acc;
    __syncthreads();
    for (int s = 128; s; s >>= 1) {
        if (tid < s) red[tid] += red[tid + s];
        __syncthreads();
    }
    if (tid == 0) {
        if (j < 128) d_g[j] = red[0];
        else d_Z = red[0];
    }
}

// ---------------- final --------------------------------------------------------
__global__ void k_final(const float* __restrict__ cls_w,
                        const float* __restrict__ cls_b,
                        float* __restrict__ out) {
    int c = threadIdx.x;
    if (c < NCLS) {
        float invZ = 1.f / d_Z;
        float acc = cls_b[c];
        for (int k = 0; k < HID; k++)
            acc += (d_g[k] * invZ) * cls_w[k * NCLS + c];
        out[c] = acc;
    }
}

// ---------------- launch ---------------------------------------------------------
extern "C" void kernel_launch(void* const* d_in, const int* in_sizes, int n_in,
                              void* d_out, int out_size) {
    const float* x     = (const float*)d_in[0];
    const int*   erows = (const int*)  d_in[1];
    const int*   ecols = (const int*)  d_in[2];
    const float* evals = (const float*)d_in[3];
    const float* fc1_w = (const float*)d_in[4];
    const float* fc1_b = (const float*)d_in[5];
    const float* fc2_w = (const float*)d_in[6];
    const float* fc2_b = (const float*)d_in[7];
    const float* att_w = (const float*)d_in[8];
    const float* att_b = (const float*)d_in[9];
    const float* cls_w = (const float*)d_in[10];
    const float* cls_b = (const float*)d_in[11];
    float* out = (float*)d_out;

    __half* pA1 = nullptr; __half* pA2 = nullptr;
    __half* pW1 = nullptr; __half* pW2 = nullptr;
    cudaGetSymbolAddress((void**)&pA1, d_A1h);
    cudaGetSymbolAddress((void**)&pA2, d_A2h);
    cudaGetSymbolAddress((void**)&pW1, d_w1t);
    cudaGetSymbolAddress((void**)&pW2, d_w2t);

    const int extras = (128 * 4 + 8 + 2) * 4;
    const int smem1 = 128 * IND * 2 * 2 + extras;
    const int smem2 = 128 * HID * 2 * 2 + extras;
    cudaFuncSetAttribute(k_gemm_mma<IND, false>,
                         cudaFuncAttributeMaxDynamicSharedMemorySize, smem1);
    cudaFuncSetAttribute(k_gemm_mma<HID, true>,
                         cudaFuncAttributeMaxDynamicSharedMemorySize, smem2);

    k_prologue<<<PB1 + PB2 + PB3, 256>>>(erows, ecols, evals, x, fc1_w, fc2_w);
    k_spmm64<<<(NN + 1) / 2, 64>>>();
    k_gemm_mma<IND, false><<<NB, 256, smem1>>>(pA1, pW1, fc1_b, nullptr, nullptr);
    k_spmm128<<<(NN + 1) / 2, 64>>>();
    k_gemm_mma<HID, true><<<NB, 256, smem2>>>(pA2, pW2, fc2_b, att_w, att_b);
    k_combine<<<129, 256>>>();
    k_final<<<1, 32>>>(cls_w, cls_b, out);
}

// round 16
// speedup vs baseline: 1.0363x; 1.0151x over previous
#include <cuda_runtime.h>
#include <cuda_fp16.h>
#include <math.h>
#include <float.h>

#define NN 100000
#define EE 3200000
#define IND 64
#define HID 128
#define NCLS 10
#define NB ((NN + 127) / 128)

// prologue block ranges
#define PB1 ((EE + 255) / 256)
#define PB2 ((NN * IND / 4 + 255) / 256)
#define PB3 ((128 * (IND + HID) + 255) / 256)

// ---------------- scratch (device globals) ----------------------------------
__device__ __align__(16) __half d_xh [(size_t)NN * IND];
__device__ __align__(16) __half d_A1h[(size_t)NN * IND];
__device__ __align__(16) __half d_h1h[(size_t)NN * HID];
__device__ __align__(16) __half d_A2h[(size_t)NN * HID];
__device__ __align__(16) __half d_w1t[HID * IND];
__device__ __align__(16) __half d_w2t[HID * HID];
__device__ __align__(16) int2  d_epack[EE];
__device__ float d_rowsum[NN];
__device__ int   d_rowptr[NN + 1];
__device__ float d_part[(size_t)NB * 130];
__device__ float d_g[HID];
__device__ float d_Z;
__device__ int   d_ctr;

// ---------------- mma helpers -------------------------------------------------
__device__ __forceinline__ void ldsm4(unsigned& r0, unsigned& r1,
                                      unsigned& r2, unsigned& r3, unsigned addr) {
    asm volatile("ldmatrix.sync.aligned.m8n8.x4.shared.b16 {%0,%1,%2,%3}, [%4];"
                 : "=r"(r0), "=r"(r1), "=r"(r2), "=r"(r3) : "r"(addr));
}
__device__ __forceinline__ void mma16816(float* c,
                                         unsigned a0, unsigned a1, unsigned a2, unsigned a3,
                                         unsigned b0, unsigned b1) {
    asm volatile("mma.sync.aligned.m16n8k16.row.col.f32.f16.f16.f32 "
                 "{%0,%1,%2,%3}, {%4,%5,%6,%7}, {%8,%9}, {%0,%1,%2,%3};"
                 : "+f"(c[0]), "+f"(c[1]), "+f"(c[2]), "+f"(c[3])
                 : "r"(a0), "r"(a1), "r"(a2), "r"(a3), "r"(b0), "r"(b1));
}

// ---------------- prologue -----------------------------------------------------
__global__ void k_prologue(const int* __restrict__ erows,
                           const int* __restrict__ ecols,
                           const float* __restrict__ evals,
                           const float* __restrict__ x,
                           const float* __restrict__ fc1_w,
                           const float* __restrict__ fc2_w) {
    int bid = blockIdx.x, tid = threadIdx.x;
    if (bid == 0 && tid == 0) d_ctr = 0;   // reset last-block counter each replay
    if (bid < PB1) {
        int i = bid * 256 + tid;
        if (i >= EE) return;
        d_epack[i] = make_int2(__ldg(ecols + i), __float_as_int(__ldg(evals + i)));
        int r1 = erows[i];
        int r0 = (i == 0) ? -1 : erows[i - 1];
        for (int r = r0 + 1; r <= r1; r++) d_rowptr[r] = i;
        if (i == EE - 1)
            for (int r = r1 + 1; r <= NN; r++) d_rowptr[r] = EE;
    } else if (bid < PB1 + PB2) {
        int i = (bid - PB1) * 256 + tid;
        if (i >= NN * IND / 4) return;
        float4 v = ((const float4*)x)[i];
        __half2 a = __floats2half2_rn(v.x, v.y);
        __half2 b = __floats2half2_rn(v.z, v.w);
        ((uint2*)d_xh)[i] = make_uint2(*(unsigned*)&a, *(unsigned*)&b);
    } else {
        int i = (bid - PB1 - PB2) * 256 + tid;
        if (i < 128 * IND) {
            int n = i / IND, k = i % IND;
            d_w1t[i] = __float2half(fc1_w[k * 128 + n]);
        } else if (i < 128 * (IND + HID)) {
            int j = i - 128 * IND;
            int n = j / HID, k = j % HID;
            d_w2t[j] = __float2half(fc2_w[k * 128 + n]);
        }
    }
}

// ---------------- gather FMA helper -------------------------------------------
__device__ __forceinline__ void fmaacc8(float* acc, const uint4& raw, float v) {
    const __half2* hp = (const __half2*)&raw;
#pragma unroll
    for (int j = 0; j < 4; j++) {
        float2 f = __half22float2(hp[j]);
        acc[2 * j]     += v * f.x;
        acc[2 * j + 1] += v * f.y;
    }
}

// ---------------- SpMM 64-wide: 8 lanes/edge, 16 edges/iter, 64-thr blocks ---
__global__ void k_spmm64() {
    int row = blockIdx.x * 2 + (threadIdx.x >> 5);
    if (row >= NN) return;
    const int lane = threadIdx.x & 31;
    const int grp = lane >> 3;
    const int boff = (lane & 7) * 8;
    const int s = d_rowptr[row], e = d_rowptr[row + 1];
    float acc[8];
#pragma unroll
    for (int j = 0; j < 8; j++) acc[j] = 0.f;
    float vs = 0.f;
    int i = s;
    for (; i + 16 <= e; i += 16) {
        int2 cv0 = __ldg(&d_epack[i      + grp]);
        int2 cv1 = __ldg(&d_epack[i + 4  + grp]);
        int2 cv2 = __ldg(&d_epack[i + 8  + grp]);
        int2 cv3 = __ldg(&d_epack[i + 12 + grp]);
        uint4 r0 = *(const uint4*)(d_xh + (size_t)cv0.x * IND + boff);
        uint4 r1 = *(const uint4*)(d_xh + (size_t)cv1.x * IND + boff);
        uint4 r2 = *(const uint4*)(d_xh + (size_t)cv2.x * IND + boff);
        uint4 r3 = *(const uint4*)(d_xh + (size_t)cv3.x * IND + boff);
        float v0 = __int_as_float(cv0.y), v1 = __int_as_float(cv1.y);
        float v2 = __int_as_float(cv2.y), v3 = __int_as_float(cv3.y);
        fmaacc8(acc, r0, v0);
        fmaacc8(acc, r1, v1);
        fmaacc8(acc, r2, v2);
        fmaacc8(acc, r3, v3);
        vs += (v0 + v1) + (v2 + v3);
    }
    for (; i < e; i += 4) {
        int idx = i + grp;
        int2 cv = (idx < e) ? __ldg(&d_epack[idx]) : make_int2(0, 0);
        float v = __int_as_float(cv.y);
        uint4 raw = *(const uint4*)(d_xh + (size_t)cv.x * IND + boff);
        fmaacc8(acc, raw, v);
        vs += v;
    }
#pragma unroll
    for (int j = 0; j < 8; j++) {
        acc[j] += __shfl_xor_sync(0xFFFFFFFFu, acc[j], 8);
        acc[j] += __shfl_xor_sync(0xFFFFFFFFu, acc[j], 16);
    }
    if (lane < 8) {
        __half2 h0 = __floats2half2_rn(acc[0], acc[1]);
        __half2 h1 = __floats2half2_rn(acc[2], acc[3]);
        __half2 h2 = __floats2half2_rn(acc[4], acc[5]);
        __half2 h3 = __floats2half2_rn(acc[6], acc[7]);
        *(uint4*)(d_A1h + (size_t)row * IND + lane * 8) =
            make_uint4(*(unsigned*)&h0, *(unsigned*)&h1,
                       *(unsigned*)&h2, *(unsigned*)&h3);
    }
    vs += __shfl_xor_sync(0xFFFFFFFFu, vs, 8);
    vs += __shfl_xor_sync(0xFFFFFFFFu, vs, 16);
    if (lane == 0) d_rowsum[row] = vs;
}

// ---------------- SpMM 128-wide: 16 lanes/edge, 8 edges/iter, 64-thr blocks --
__global__ void k_spmm128() {
    int row = blockIdx.x * 2 + (threadIdx.x >> 5);
    if (row >= NN) return;
    const int lane = threadIdx.x & 31;
    const int half = lane >> 4;
    const int boff = (lane & 15) * 8;
    const int s = d_rowptr[row], e = d_rowptr[row + 1];
    float acc[8];
#pragma unroll
    for (int j = 0; j < 8; j++) acc[j] = 0.f;
    int i = s;
    for (; i + 8 <= e; i += 8) {
        int2 cv0 = __ldg(&d_epack[i     + half]);
        int2 cv1 = __ldg(&d_epack[i + 2 + half]);
        int2 cv2 = __ldg(&d_epack[i + 4 + half]);
        int2 cv3 = __ldg(&d_epack[i + 6 + half]);
        uint4 r0 = *(const uint4*)(d_h1h + (size_t)cv0.x * HID + boff);
        uint4 r1 = *(const uint4*)(d_h1h + (size_t)cv1.x * HID + boff);
        uint4 r2 = *(const uint4*)(d_h1h + (size_t)cv2.x * HID + boff);
        uint4 r3 = *(const uint4*)(d_h1h + (size_t)cv3.x * HID + boff);
        fmaacc8(acc, r0, __int_as_float(cv0.y));
        fmaacc8(acc, r1, __int_as_float(cv1.y));
        fmaacc8(acc, r2, __int_as_float(cv2.y));
        fmaacc8(acc, r3, __int_as_float(cv3.y));
    }
    for (; i < e; i += 2) {
        int idx = i + half;
        int2 cv = (idx < e) ? __ldg(&d_epack[idx]) : make_int2(0, 0);
        uint4 raw = *(const uint4*)(d_h1h + (size_t)cv.x * HID + boff);
        fmaacc8(acc, raw, __int_as_float(cv.y));
    }
#pragma unroll
    for (int j = 0; j < 8; j++)
        acc[j] += __shfl_xor_sync(0xFFFFFFFFu, acc[j], 16);
    if (lane < 16) {
        __half2 h0 = __floats2half2_rn(acc[0], acc[1]);
        __half2 h1 = __floats2half2_rn(acc[2], acc[3]);
        __half2 h2 = __floats2half2_rn(acc[4], acc[5]);
        __half2 h3 = __floats2half2_rn(acc[6], acc[7]);
        *(uint4*)(d_A2h + (size_t)row * HID + lane * 8) =
            make_uint4(*(unsigned*)&h0, *(unsigned*)&h1,
                       *(unsigned*)&h2, *(unsigned*)&h3);
    }
}

// ---------------- tensor-core GEMM --------------------------------------------
template <int K, bool SECOND>
__global__ void __launch_bounds__(256, 2)
k_gemm_mma(const __half* __restrict__ Ag, const __half* __restrict__ Wt,
           const float* __restrict__ bias,
           const float* __restrict__ att_w, const float* __restrict__ att_b) {
    extern __shared__ __align__(16) char smraw[];
    __half* A_sh = (__half*)smraw;
    __half* W_sh = A_sh + 128 * K;
    float* bias_sh = (float*)(W_sh + 128 * K);
    float* aw_sh = bias_sh + 128;
    float* s_sh  = aw_sh + 128;
    float* g_sh  = s_sh + 128;
    float* wmax  = g_sh + 128;
    float* m_sh  = wmax + 8;
    float* z_sh  = m_sh + 1;

    const int tid = threadIdx.x;
    const int r0 = blockIdx.x * 128;
    const int w = tid >> 5, lane = tid & 31;
    const int q = lane & 3, g8 = lane >> 2;

    if (tid < 128) {
        bias_sh[tid] = bias[tid];
        if (SECOND) { aw_sh[tid] = att_w[tid]; g_sh[tid] = 0.f; }
    }
    if (SECOND && tid == 128) z_sh[0] = 0.f;

    constexpr int GPR = K / 8;
    {
        const uint4* src = (const uint4*)Ag;
#pragma unroll
        for (int i = 0; i < 128 * GPR / 256; i++) {
            int idx = i * 256 + tid;
            int row = idx / GPR, g = idx % GPR;
            int gr = r0 + row;
            uint4 v = make_uint4(0, 0, 0, 0);
            if (gr < NN) v = src[(size_t)gr * GPR + g];
            *(uint4*)&A_sh[row * K + ((g ^ (row & 7)) << 3)] = v;
        }
        const uint4* ws = (const uint4*)Wt;
#pragma unroll
        for (int i = 0; i < 128 * GPR / 256; i++) {
            int idx = i * 256 + tid;
            int row = idx / GPR, g = idx % GPR;
            *(uint4*)&W_sh[row * K + ((g ^ (row & 7)) << 3)] = ws[idx];
        }
    }
    __syncthreads();

    unsigned aBase = (unsigned)__cvta_generic_to_shared(A_sh);
    unsigned wBase = (unsigned)__cvta_generic_to_shared(W_sh);

    const int rowA   = w * 16 + ((lane >> 3) & 1) * 8 + (lane & 7);
    const int khalfA = lane >> 4;
    const int rowBoff = ((lane >> 4) & 1) * 8 + (lane & 7);
    const int khalfB  = (lane >> 3) & 1;
    const int l7 = lane & 7;

    float acc[16][4];
#pragma unroll
    for (int t = 0; t < 16; t++)
#pragma unroll
        for (int p = 0; p < 4; p++) acc[t][p] = 0.f;

#pragma unroll
    for (int kc = 0; kc < K; kc += 16) {
        unsigned a0, a1, a2, a3;
        int grpA = (kc >> 3) + khalfA;
        ldsm4(a0, a1, a2, a3,
              aBase + (unsigned)(rowA * K + ((grpA ^ (rowA & 7)) << 3)) * 2u);
        int grpB = (kc >> 3) + khalfB;
#pragma unroll
        for (int jj = 0; jj < 8; jj++) {
            int rowB = jj * 16 + rowBoff;
            unsigned b0, b1, b2, b3;
            ldsm4(b0, b1, b2, b3,
                  wBase + (unsigned)(rowB * K + ((grpB ^ l7) << 3)) * 2u);
            mma16816(acc[2 * jj],     a0, a1, a2, a3, b0, b1);
            mma16816(acc[2 * jj + 1], a0, a1, a2, a3, b2, b3);
        }
    }

    const int lr0 = w * 16 + g8, lr1 = lr0 + 8;
    const int gr0 = r0 + lr0, gr1 = r0 + lr1;
    const float rs0 = (gr0 < NN) ? d_rowsum[gr0] : 0.f;
    const float rs1 = (gr1 < NN) ? d_rowsum[gr1] : 0.f;

#pragma unroll
    for (int t = 0; t < 16; t++) {
#pragma unroll
        for (int p = 0; p < 2; p++) {
            float b = bias_sh[8 * t + 2 * q + p];
            acc[t][p]     = fmaxf(acc[t][p]     + rs0 * b, 0.f);
            acc[t][2 + p] = fmaxf(acc[t][2 + p] + rs1 * b, 0.f);
        }
    }

    if (!SECOND) {
#pragma unroll
        for (int t = 0; t < 16; t++) {
            int col = 8 * t + 2 * q;
            if (gr0 < NN) {
                __half2 h = __floats2half2_rn(acc[t][0], acc[t][1]);
                *(__half2*)&d_h1h[(size_t)gr0 * HID + col] = h;
            }
            if (gr1 < NN) {
                __half2 h = __floats2half2_rn(acc[t][2], acc[t][3]);
                *(__half2*)&d_h1h[(size_t)gr1 * HID + col] = h;
            }
        }
        return;
    } else {
        float sc0 = 0.f, sc1 = 0.f;
#pragma unroll
        for (int t = 0; t < 16; t++) {
            int col = 8 * t + 2 * q;
            if (gr0 < NN) {
                float2 f = __half22float2(*(const __half2*)&d_h1h[(size_t)gr0 * HID + col]);
                acc[t][0] += f.x; acc[t][1] += f.y;
            }
            if (gr1 < NN) {
                float2 f = __half22float2(*(const __half2*)&d_h1h[(size_t)gr1 * HID + col]);
                acc[t][2] += f.x; acc[t][3] += f.y;
            }
            float aw0 = aw_sh[col], aw1 = aw_sh[col + 1];
            sc0 += acc[t][0] * aw0 + acc[t][1] * aw1;
            sc1 += acc[t][2] * aw0 + acc[t][3] * aw1;
        }
        sc0 += __shfl_xor_sync(0xFFFFFFFFu, sc0, 1);
        sc0 += __shfl_xor_sync(0xFFFFFFFFu, sc0, 2);
        sc1 += __shfl_xor_sync(0xFFFFFFFFu, sc1, 1);
        sc1 += __shfl_xor_sync(0xFFFFFFFFu, sc1, 2);
        float ab = att_b[0];
        if (q == 0) {
            s_sh[lr0] = (gr0 < NN) ? (sc0 + ab) : -FLT_MAX;
            s_sh[lr1] = (gr1 < NN) ? (sc1 + ab) : -FLT_MAX;
        }
        __syncthreads();
        {
            float v = s_sh[tid & 127];
#pragma unroll
            for (int off = 16; off; off >>= 1)
                v = fmaxf(v, __shfl_xor_sync(0xFFFFFFFFu, v, off));
            if (lane == 0) wmax[w] = v;
        }
        __syncthreads();
        if (tid == 0) {
            float m = wmax[0];
#pragma unroll
            for (int i = 1; i < 8; i++) m = fmaxf(m, wmax[i]);
            m_sh[0] = m;
        }
        __syncthreads();
        const float mb = m_sh[0];
        const float e0 = __expf(s_sh[lr0] - mb);
        const float e1 = __expf(s_sh[lr1] - mb);
#pragma unroll
        for (int t = 0; t < 16; t++) {
            acc[t][0] = e0 * acc[t][0] + e1 * acc[t][2];
            acc[t][1] = e0 * acc[t][1] + e1 * acc[t][3];
        }
#pragma unroll
        for (int off = 4; off <= 16; off <<= 1) {
#pragma unroll
            for (int t = 0; t < 16; t++) {
                acc[t][0] += __shfl_xor_sync(0xFFFFFFFFu, acc[t][0], off);
                acc[t][1] += __shfl_xor_sync(0xFFFFFFFFu, acc[t][1], off);
            }
        }
        if (lane < 4) {
#pragma unroll
            for (int t = 0; t < 16; t++) {
                atomicAdd(&g_sh[8 * t + 2 * lane],     acc[t][0]);
                atomicAdd(&g_sh[8 * t + 2 * lane + 1], acc[t][1]);
            }
        }
        float ze = (q == 0) ? (e0 + e1) : 0.f;
        ze += __shfl_xor_sync(0xFFFFFFFFu, ze, 4);
        ze += __shfl_xor_sync(0xFFFFFFFFu, ze, 8);
        ze += __shfl_xor_sync(0xFFFFFFFFu, ze, 16);
        if (lane == 0) atomicAdd(z_sh, ze);
        __syncthreads();
        float* pp = d_part + (size_t)blockIdx.x * 130;
        if (tid < 128) pp[tid] = g_sh[tid];
        if (tid == 128) pp[128] = z_sh[0];
        if (tid == 129) pp[129] = m_sh[0];
    }
}

// ---------------- combine + fused final (last-block pattern) -----------------
__global__ void k_combine(const float* __restrict__ cls_w,
                          const float* __restrict__ cls_b,
                          float* __restrict__ out) {
    __shared__ float red[256];
    __shared__ float Msh;
    __shared__ bool amLast;
    int tid = threadIdx.x, j = blockIdx.x;
    float lm = -FLT_MAX;
    for (int b = tid; b < NB; b += 256)
        lm = fmaxf(lm, d_part[(size_t)b * 130 + 129]);
    red[tid] = lm;
    __syncthreads();
    for (int s = 128; s; s >>= 1) {
        if (tid < s) red[tid] = fmaxf(red[tid], red[tid + s]);
        __syncthreads();
    }
    if (tid == 0) Msh = red[0];
    __syncthreads();
    float M = Msh;
    int col = (j < 128) ? j : 128;
    float acc = 0.f;
    for (int b = tid; b < NB; b += 256) {
        float mb = d_part[(size_t)b * 130 + 129];
        acc += __expf(mb - M) * d_part[(size_t)b * 130 + col];
    }
    red[tid] = acc;
    __syncthreads();
    for (int s = 128; s; s >>= 1) {
        if (tid < s) red[tid] += red[tid + s];
        __syncthreads();
    }
    if (tid == 0) {
        if (j < 128) d_g[j] = red[0];
        else d_Z = red[0];
        __threadfence();
        int old = atomicAdd(&d_ctr, 1);
        amLast = (old == gridDim.x - 1);
    }
    __syncthreads();
    // Last block to finish computes the final classifier output.
    if (amLast && tid < NCLS) {
        float invZ = 1.f / d_Z;
        float a = cls_b[tid];
        for (int k = 0; k < HID; k++)
            a += (d_g[k] * invZ) * cls_w[k * NCLS + tid];
        out[tid] = a;
    }
}

// ---------------- launch ---------------------------------------------------------
extern "C" void kernel_launch(void* const* d_in, const int* in_sizes, int n_in,
                              void* d_out, int out_size) {
    const float* x     = (const float*)d_in[0];
    const int*   erows = (const int*)  d_in[1];
    const int*   ecols = (const int*)  d_in[2];
    const float* evals = (const float*)d_in[3];
    const float* fc1_w = (const float*)d_in[4];
    const float* fc1_b = (const float*)d_in[5];
    const float* fc2_w = (const float*)d_in[6];
    const float* fc2_b = (const float*)d_in[7];
    const float* att_w = (const float*)d_in[8];
    const float* att_b = (const float*)d_in[9];
    const float* cls_w = (const float*)d_in[10];
    const float* cls_b = (const float*)d_in[11];
    float* out = (float*)d_out;

    __half* pA1 = nullptr; __half* pA2 = nullptr;
    __half* pW1 = nullptr; __half* pW2 = nullptr;
    cudaGetSymbolAddress((void**)&pA1, d_A1h);
    cudaGetSymbolAddress((void**)&pA2, d_A2h);
    cudaGetSymbolAddress((void**)&pW1, d_w1t);
    cudaGetSymbolAddress((void**)&pW2, d_w2t);

    const int extras = (128 * 4 + 8 + 2) * 4;
    const int smem1 = 128 * IND * 2 * 2 + extras;
    const int smem2 = 128 * HID * 2 * 2 + extras;
    cudaFuncSetAttribute(k_gemm_mma<IND, false>,
                         cudaFuncAttributeMaxDynamicSharedMemorySize, smem1);
    cudaFuncSetAttribute(k_gemm_mma<HID, true>,
                         cudaFuncAttributeMaxDynamicSharedMemorySize, smem2);

    k_prologue<<<PB1 + PB2 + PB3, 256>>>(erows, ecols, evals, x, fc1_w, fc2_w);
    k_spmm64<<<(NN + 1) / 2, 64>>>();
    k_gemm_mma<IND, false><<<NB, 256, smem1>>>(pA1, pW1, fc1_b, nullptr, nullptr);
    k_spmm128<<<(NN + 1) / 2, 64>>>();
    k_gemm_mma<HID, true><<<NB, 256, smem2>>>(pA2, pW2, fc2_b, att_w, att_b);
    k_combine<<<129, 256>>>(cls_w, cls_b, out);
}